// round 14
// baseline (speedup 1.0000x reference)
#include <cuda_runtime.h>
#include <cstdint>

#define TT   16384
#define ED   1024
#define HD   1024
#define G4   4096
#define NMV  128        // matvec CTAs (each owns 8 h-indices = 32 gate rows)
#define NLOSS 16        // dedicated loss CTAs
#define RTHREADS 512

// ---- scratch (static device memory; no allocations anywhere) ----
__device__ float        g_xg[TT][G4];       // 256 MB: input projections
__device__ float        g_h[TT][HD];        // 64 MB: h history (single buffer)
__device__ unsigned int g_cnt[TT][32];      // 2 MB: per-step counter, ONE per 128B line
__device__ float        g_loss[TT];         // per-step losses
__device__ int          g_ys[TT];           // normalized labels (int32)

// ---- helpers ----
__device__ __forceinline__ unsigned long long ffma2(unsigned long long a,
                                                    unsigned long long b,
                                                    unsigned long long c) {
    unsigned long long d;
    asm("fma.rn.f32x2 %0, %1, %2, %3;" : "=l"(d) : "l"(a), "l"(b), "l"(c));
    return d;
}
__device__ __forceinline__ float2 unpk(unsigned long long v) {
    float2 r;
    asm("mov.b64 {%0, %1}, %2;" : "=f"(r.x), "=f"(r.y) : "l"(v));
    return r;
}
__device__ __forceinline__ unsigned long long pk2(float lo, float hi) {
    unsigned long long v;
    asm("mov.b64 %0, {%1, %2};" : "=l"(v) : "f"(lo), "f"(hi));
    return v;
}
__device__ __forceinline__ unsigned int ld_acq(const unsigned int* p) {
    unsigned int v;
    asm volatile("ld.acquire.gpu.global.u32 %0, [%1];" : "=r"(v) : "l"(p) : "memory");
    return v;
}
__device__ __forceinline__ unsigned int ld_rlx(const unsigned int* p) {
    unsigned int v;
    asm volatile("ld.relaxed.gpu.global.u32 %0, [%1];" : "=r"(v) : "l"(p) : "memory");
    return v;
}
__device__ __forceinline__ void red_rel(unsigned int* p) {
    asm volatile("red.release.gpu.global.add.u32 [%0], 1;" :: "l"(p) : "memory");
}
// tid0-only wait: counts <=128 (7-bit until done), so OR>=NMV <=> any ==NMV
__device__ __forceinline__ void wait_cnt(const unsigned int* p) {
    for (;;) {
        unsigned int a = ld_rlx(p);
        unsigned int b = ld_rlx(p);
        unsigned int c = ld_rlx(p);
        unsigned int d = ld_rlx(p);
        if ((a | b | c | d) >= NMV) break;
    }
    (void)ld_acq(p);   // acquire ordering for subsequent h reads
}
__device__ __forceinline__ float ex2f(float x) {
    float y; asm("ex2.approx.f32 %0, %1;" : "=f"(y) : "f"(x)); return y;
}
__device__ __forceinline__ float rcpf(float x) {
    float y; asm("rcp.approx.f32 %0, %1;" : "=f"(y) : "f"(x)); return y;
}
#define L2E 1.4426950408889634f
__device__ __forceinline__ float sigm(float x) {           // 1/(1+e^-x)
    return rcpf(1.f + ex2f(-x * L2E));
}
__device__ __forceinline__ float tanha(float x) {          // 1 - 2/(e^{2x}+1)
    return fmaf(-2.f, rcpf(1.f + ex2f(x * (2.f * L2E))), 1.f);
}

// ---- kernel 0: reset padded counters ----
__global__ void __launch_bounds__(256) reset_cnt() {
    (&g_cnt[0][0])[blockIdx.x * 256 + threadIdx.x] = 0u;   // TT*32 words
}
// ---- kernel 0b: normalize ys dtype (int64 vs int32 autodetect) ----
__global__ void __launch_bounds__(256) reset_ys(const int* __restrict__ ysr) {
    int i = blockIdx.x * 256 + threadIdx.x;
    bool is64 = true;
#pragma unroll
    for (int q = 1; q < 16; q += 2) is64 = is64 && (ysr[q] == 0);
    if (i < TT) g_ys[i] = is64 ? ysr[2 * i] : ysr[i];
}

// ---- kernel 1: xg = Xs @ W_ih^T + (b_ih + b_hh), pipelined f32x2 GEMM ----
// (R8-proven version: next slab's global loads issued right after the bar.)
__global__ void __launch_bounds__(256) gemm_xg(const float* __restrict__ X,
                                               const float* __restrict__ W,
                                               const float* __restrict__ bih,
                                               const float* __restrict__ bhh) {
    __shared__ float As[8][128];
    __shared__ float Bs[8][128];
    const int tid = threadIdx.x;
    const int tx = tid & 15, ty = tid >> 4;
    const int bm = blockIdx.y * 128;
    const int bn = blockIdx.x * 128;
    const int lr = tid >> 1;            // 0..127
    const int lc = (tid & 1) << 2;      // 0 or 4
    const float* Ag = X + (size_t)(bm + lr) * ED + lc;
    const float* Bg = W + (size_t)(bn + lr) * ED + lc;

    unsigned long long acc2[8][4];
#pragma unroll
    for (int i = 0; i < 8; i++)
#pragma unroll
        for (int j = 0; j < 4; j++) acc2[i][j] = 0ull;

    float4 av = *(const float4*)(Ag);
    float4 bv = *(const float4*)(Bg);
    for (int k0 = 0; k0 < ED; k0 += 8) {
        __syncthreads();   // previous compute done reading smem
        As[lc + 0][lr] = av.x; As[lc + 1][lr] = av.y;
        As[lc + 2][lr] = av.z; As[lc + 3][lr] = av.w;
        Bs[lc + 0][lr] = bv.x; Bs[lc + 1][lr] = bv.y;
        Bs[lc + 2][lr] = bv.z; Bs[lc + 3][lr] = bv.w;
        __syncthreads();
        if (k0 + 8 < ED) {                     // prefetch next slab NOW
            av = *(const float4*)(Ag + k0 + 8);
            bv = *(const float4*)(Bg + k0 + 8);
        }
#pragma unroll
        for (int kk = 0; kk < 8; kk++) {
            float a[8];
            *(float4*)(a)     = *(const float4*)&As[kk][ty * 8];
            *(float4*)(a + 4) = *(const float4*)&As[kk][ty * 8 + 4];
            ulonglong2 b01 = *(const ulonglong2*)&Bs[kk][tx * 8];
            ulonglong2 b23 = *(const ulonglong2*)&Bs[kk][tx * 8 + 4];
#pragma unroll
            for (int i = 0; i < 8; i++) {
                unsigned long long ad = pk2(a[i], a[i]);
                acc2[i][0] = ffma2(ad, b01.x, acc2[i][0]);
                acc2[i][1] = ffma2(ad, b01.y, acc2[i][1]);
                acc2[i][2] = ffma2(ad, b23.x, acc2[i][2]);
                acc2[i][3] = ffma2(ad, b23.y, acc2[i][3]);
            }
        }
    }

    const int n0 = bn + tx * 8;
    float bias[8];
#pragma unroll
    for (int j = 0; j < 8; j++) bias[j] = bih[n0 + j] + bhh[n0 + j];
#pragma unroll
    for (int i = 0; i < 8; i++) {
        const int m = bm + ty * 8 + i;
        float2 c0 = unpk(acc2[i][0]), c1 = unpk(acc2[i][1]);
        float2 c2 = unpk(acc2[i][2]), c3 = unpk(acc2[i][3]);
        float4 o0 = make_float4(c0.x + bias[0], c0.y + bias[1],
                                c1.x + bias[2], c1.y + bias[3]);
        float4 o1 = make_float4(c2.x + bias[4], c2.y + bias[5],
                                c3.x + bias[6], c3.y + bias[7]);
        *(float4*)&g_xg[m][n0]     = o0;
        *(float4*)&g_xg[m][n0 + 4] = o1;
    }
}

// ---- kernel 2: persistent LSTM recurrence + loss (R8 skeleton, 1 h buffer) ----
// Publish: lanes 0-7 store hv (one 32B segment on ONE line) then lane0
// red.release -> the release fence drains ONE line (vs 4 slices with the
// replica scheme). Detect: tid0 polls one padded counter word, bar fanout.
__global__ void __launch_bounds__(RTHREADS, 1) lstm_persist(const float* __restrict__ Whh) {
    const int b   = blockIdx.x;
    const int tid = threadIdx.x;

    if (b < NMV) {
        __shared__ float part[16][32];
        const int w = tid >> 5, l = tid & 31;
        // lane l -> gate (l>>3) in {i,f,g,o}, local row j = l&7; global j = 8b+(l&7)
        const int row = ((l >> 3) << 10) + (b << 3) + (l & 7);

        // This thread's 64 W_hh values in registers (cols 64w .. 64w+63).
        ulonglong2 Wr[16];
        {
            const ulonglong2* wp =
                (const ulonglong2*)(Whh + (size_t)row * HD + (w << 6));
#pragma unroll
            for (int q = 0; q < 16; q++) Wr[q] = wp[q];
        }
        float cstate = 0.f;              // warp0: replicated across 8-lane groups
        float xcur = 0.f;
        if (w == 0) xcur = g_xg[0][row];

        for (int t = 0; t < TT; t++) {
            if (t > 0) {
                if (tid == 0) wait_cnt(&g_cnt[t - 1][0]);
                __syncthreads();         // fan out: h_{t-1} visible
            }
            float psum = 0.f;
            if (t > 0) {
                const ulonglong2* hp =
                    (const ulonglong2*)(&g_h[t - 1][w << 6]);
                unsigned long long a0 = 0ull, a1 = 0ull;
#pragma unroll
                for (int q = 0; q < 16; q++) {
                    ulonglong2 hh = hp[q];           // LDG.128, warp-uniform addr
                    a0 = ffma2(Wr[q].x, hh.x, a0);
                    a1 = ffma2(Wr[q].y, hh.y, a1);
                }
                float2 p0 = unpk(a0), p1 = unpk(a1);
                psum = (p0.x + p1.x) + (p0.y + p1.y);
            }
            part[w][l] = psum;
            __syncthreads();  // partials of step t visible to warp0

            if (w == 0) {
                float s0 = part[0][l]  + part[1][l];
                float s1 = part[2][l]  + part[3][l];
                float s2 = part[4][l]  + part[5][l];
                float s3 = part[6][l]  + part[7][l];
                float s4 = part[8][l]  + part[9][l];
                float s5 = part[10][l] + part[11][l];
                float s6 = part[12][l] + part[13][l];
                float s7 = part[14][l] + part[15][l];
                float u0 = (s0 + s1) + (s2 + s3);
                float u1 = (s4 + s5) + (s6 + s7);
                float gpre = xcur + (u0 + u1);

                // xcur consumed -> issue next step's DRAM prefetch NOW
                if (t + 1 < TT) xcur = g_xg[t + 1][row];

                // lane-parallel activations: gates i,f,o -> sigmoid; g -> tanh
                float act = ((l >> 3) == 2) ? tanha(gpre) : sigm(gpre);

                const int jj = l & 7;
                float ig = __shfl_sync(0xffffffffu, act, jj);
                float fg = __shfl_sync(0xffffffffu, act, jj + 8);
                float gg = __shfl_sync(0xffffffffu, act, jj + 16);
                float og = __shfl_sync(0xffffffffu, act, jj + 24);
                cstate = fmaf(fg, cstate, ig * gg);
                float hv = og * tanha(cstate);
                if (l < 8) g_h[t][(b << 3) + jj] = hv;   // ONE 32B segment
                __syncwarp();
                if (l == 0) red_rel(&g_cnt[t][0]);       // publish (release)
            }
        }
    } else {
        // ---- loss CTA (off the critical path) ----
        __shared__ float sred[RTHREADS];
        const int lcta = b - NMV;
        for (int t = lcta; t < TT; t += NLOSS) {
            if (tid == 0) wait_cnt(&g_cnt[t][0]);
            __syncthreads();
            float v0 = g_h[t][2 * tid];
            float v1 = g_h[t][2 * tid + 1];
            sred[tid] = ex2f(v0 * L2E) + ex2f(v1 * L2E);
            __syncthreads();
            for (int s = RTHREADS / 2; s >= 32; s >>= 1) {
                if (tid < s) sred[tid] += sred[tid + s];
                __syncthreads();
            }
            if (tid < 32) {
                float v = sred[tid];
                v += __shfl_down_sync(0xffffffffu, v, 16);
                v += __shfl_down_sync(0xffffffffu, v, 8);
                v += __shfl_down_sync(0xffffffffu, v, 4);
                v += __shfl_down_sync(0xffffffffu, v, 2);
                v += __shfl_down_sync(0xffffffffu, v, 1);
                if (tid == 0) {
                    int y = g_ys[t];
                    g_loss[t] = __logf(v) - g_h[t][y];   // h in (-1,1): no max shift
                }
            }
            __syncthreads();
        }
    }
}

// ---- kernel 3: deterministic final sum ----
__global__ void __launch_bounds__(256) finalize_k(float* __restrict__ out) {
    __shared__ float sr[256];
    const int tid = threadIdx.x;
    float s = 0.f;
    for (int i = tid; i < TT; i += 256) s += g_loss[i];
    sr[tid] = s;
    __syncthreads();
    for (int st = 128; st >= 1; st >>= 1) {
        if (tid < st) sr[tid] += sr[tid + st];
        __syncthreads();
    }
    if (tid == 0) out[0] = sr[0];
}

// ---- entry point ----
extern "C" void kernel_launch(void* const* d_in, const int* in_sizes, int n_in,
                              void* d_out, int out_size) {
    const float* Xs  = (const float*)d_in[0];
    const float* Wih = (const float*)d_in[1];
    const float* Whh = (const float*)d_in[2];
    const float* bih = (const float*)d_in[3];
    const float* bhh = (const float*)d_in[4];
    const int*   ysr = (const int*)d_in[5];

    reset_cnt<<<(TT * 32) / 256, 256>>>();
    reset_ys<<<TT / 256, 256>>>(ysr);
    gemm_xg<<<dim3(G4 / 128, TT / 128), 256>>>(Xs, Wih, bih, bhh);
    lstm_persist<<<NMV + NLOSS, RTHREADS>>>(Whh);
    finalize_k<<<1, 256>>>((float*)d_out);
}

// round 15
// speedup vs baseline: 1.0830x; 1.0830x over previous
#include <cuda_runtime.h>
#include <cuda_bf16.h>
#include <cstdint>

#define TT   16384
#define ED   1024
#define HD   1024
#define G4   4096
#define NMV  128        // matvec CTAs (each owns 8 h-indices = 32 gate rows)
#define NLOSS 16        // dedicated loss CTAs
#define RTHREADS 512

// ---- scratch (static device memory; no allocations anywhere) ----
__device__ float         g_xg[TT][G4];       // 256 MB: input projections
__device__ float         g_hrep[4][TT][HD];  // 256 MB: h replicas (rep0 also feeds loss)
__device__ unsigned int  g_cnt[TT][32];      // 2 MB: per-step counter, ONE per 128B line
__device__ float         g_loss[TT];         // per-step losses
__device__ int           g_ys[TT];           // normalized labels (int32)
__device__ __nv_bfloat16 g_Xhi[TT * ED];     // bf16 splits of Xs
__device__ __nv_bfloat16 g_Xlo[TT * ED];
__device__ __nv_bfloat16 g_Whi[G4 * ED];     // bf16 splits of W_ih
__device__ __nv_bfloat16 g_Wlo[G4 * ED];

// ---- helpers ----
__device__ __forceinline__ unsigned long long ffma2(unsigned long long a,
                                                    unsigned long long b,
                                                    unsigned long long c) {
    unsigned long long d;
    asm("fma.rn.f32x2 %0, %1, %2, %3;" : "=l"(d) : "l"(a), "l"(b), "l"(c));
    return d;
}
__device__ __forceinline__ float2 unpk(unsigned long long v) {
    float2 r;
    asm("mov.b64 {%0, %1}, %2;" : "=f"(r.x), "=f"(r.y) : "l"(v));
    return r;
}
__device__ __forceinline__ unsigned int ld_acq(const unsigned int* p) {
    unsigned int v;
    asm volatile("ld.acquire.gpu.global.u32 %0, [%1];" : "=r"(v) : "l"(p) : "memory");
    return v;
}
__device__ __forceinline__ unsigned int ld_rlx(const unsigned int* p) {
    unsigned int v;
    asm volatile("ld.relaxed.gpu.global.u32 %0, [%1];" : "=r"(v) : "l"(p) : "memory");
    return v;
}
__device__ __forceinline__ void red_rel(unsigned int* p) {
    asm volatile("red.release.gpu.global.add.u32 [%0], 1;" :: "l"(p) : "memory");
}
// tid0-only wait: counts <=128 (7-bit until done), so OR>=NMV <=> any ==NMV
__device__ __forceinline__ void wait_cnt(const unsigned int* p) {
    for (;;) {
        unsigned int a = ld_rlx(p);
        unsigned int b = ld_rlx(p);
        unsigned int c = ld_rlx(p);
        unsigned int d = ld_rlx(p);
        if ((a | b | c | d) >= NMV) break;
    }
    (void)ld_acq(p);   // acquire ordering for subsequent h reads
}
__device__ __forceinline__ float ex2f(float x) {
    float y; asm("ex2.approx.f32 %0, %1;" : "=f"(y) : "f"(x)); return y;
}
__device__ __forceinline__ float rcpf(float x) {
    float y; asm("rcp.approx.f32 %0, %1;" : "=f"(y) : "f"(x)); return y;
}
#define L2E 1.4426950408889634f
__device__ __forceinline__ float sigm(float x) {           // 1/(1+e^-x)
    return rcpf(1.f + ex2f(-x * L2E));
}
__device__ __forceinline__ float tanha(float x) {          // 1 - 2/(e^{2x}+1)
    return fmaf(-2.f, rcpf(1.f + ex2f(x * (2.f * L2E))), 1.f);
}
// m16n8k16 row.col bf16 MMA, fp32 accumulate (PTX-standard since sm_80)
__device__ __forceinline__ void mma16816(float* d, const unsigned* a, const unsigned* b) {
    asm volatile("mma.sync.aligned.m16n8k16.row.col.f32.bf16.bf16.f32 "
                 "{%0,%1,%2,%3}, {%4,%5,%6,%7}, {%8,%9}, {%0,%1,%2,%3};"
                 : "+f"(d[0]), "+f"(d[1]), "+f"(d[2]), "+f"(d[3])
                 : "r"(a[0]), "r"(a[1]), "r"(a[2]), "r"(a[3]),
                   "r"(b[0]), "r"(b[1]));
}

// ---- kernel 0: reset padded counters ----
__global__ void __launch_bounds__(256) reset_cnt() {
    (&g_cnt[0][0])[blockIdx.x * 256 + threadIdx.x] = 0u;   // TT*32 words
}
// ---- kernel 0b: normalize ys dtype (int64 vs int32 autodetect) ----
__global__ void __launch_bounds__(256) reset_ys(const int* __restrict__ ysr) {
    int i = blockIdx.x * 256 + threadIdx.x;
    bool is64 = true;
#pragma unroll
    for (int q = 1; q < 16; q += 2) is64 = is64 && (ysr[q] == 0);
    if (i < TT) g_ys[i] = is64 ? ysr[2 * i] : ysr[i];
}
// ---- kernel 0c: fp32 -> (bf16 hi, bf16 lo) splits ----
__global__ void __launch_bounds__(256) prep_x(const float* __restrict__ X) {
    int i = blockIdx.x * 256 + threadIdx.x;
    float x = X[i];
    __nv_bfloat16 hi = __float2bfloat16_rn(x);
    g_Xhi[i] = hi;
    g_Xlo[i] = __float2bfloat16_rn(x - __bfloat162float(hi));
}
__global__ void __launch_bounds__(256) prep_w(const float* __restrict__ W) {
    int i = blockIdx.x * 256 + threadIdx.x;
    float x = W[i];
    __nv_bfloat16 hi = __float2bfloat16_rn(x);
    g_Whi[i] = hi;
    g_Wlo[i] = __float2bfloat16_rn(x - __bfloat162float(hi));
}

// ---- kernel 1: xg = Xs @ W_ih^T + b via bf16-split HMMA (mma.sync) ----
// CTA tile 128(M) x 64(N), 8 warps (4x2), warp tile 32x32 = 2(m16) x 4(n8).
// K chunk 64; D = Ahi*Bhi + Ahi*Blo + Alo*Bhi, fp32 accumulators.
// SMEM rows padded to 72 bf16 (144B): bank = 4*gid + tig -> conflict-free.
#define KC    64
#define SROW  144                         // smem row stride in bytes (72 bf16)
#define SM_XH 0
#define SM_XL (128 * SROW)                // 18432
#define SM_WH (2 * 128 * SROW)            // 36864
#define SM_WL (SM_WH + 64 * SROW)         // 46080
#define SM_GEMM (SM_WL + 64 * SROW)       // 55296 bytes dynamic smem

__global__ void __launch_bounds__(256) gemm_mma(const float* __restrict__ bih,
                                                const float* __restrict__ bhh) {
    extern __shared__ char sm[];
    const int tid  = threadIdx.x;
    const int bn   = blockIdx.x * 64;     // gate rows (N)
    const int bm   = blockIdx.y * 128;    // T rows (M)
    const int lane = tid & 31;
    const int ww   = tid >> 5;
    const int gid  = lane >> 2, tig = lane & 3;
    const int wm   = ww & 3,  wn  = ww >> 2;

    float acc[2][4][4];
#pragma unroll
    for (int mt = 0; mt < 2; mt++)
#pragma unroll
        for (int nt = 0; nt < 4; nt++)
#pragma unroll
            for (int r = 0; r < 4; r++) acc[mt][nt][r] = 0.f;

    const int xr = tid >> 1, xh = tid & 1;     // X copy: row, 32-col half
    const int wr = tid >> 2, wq = tid & 3;     // W copy: row, 16-col quarter

    for (int kc = 0; kc < ED; kc += KC) {
        __syncthreads();                       // previous compute done with smem
        {   // X slabs: 128 rows x 64 cols bf16 (hi & lo)
            size_t gs = ((size_t)(bm + xr) << 10) + kc + (xh << 5);
            const uint4* sh = (const uint4*)&g_Xhi[gs];
            const uint4* sl = (const uint4*)&g_Xlo[gs];
            uint4* dh = (uint4*)(sm + SM_XH + xr * SROW + (xh << 6));
            uint4* dl = (uint4*)(sm + SM_XL + xr * SROW + (xh << 6));
#pragma unroll
            for (int i = 0; i < 4; i++) { dh[i] = sh[i]; dl[i] = sl[i]; }
        }
        {   // W slabs: 64 rows x 64 cols bf16 (hi & lo)
            size_t gs = ((size_t)(bn + wr) << 10) + kc + (wq << 4);
            const uint4* sh = (const uint4*)&g_Whi[gs];
            const uint4* sl = (const uint4*)&g_Wlo[gs];
            uint4* dh = (uint4*)(sm + SM_WH + wr * SROW + (wq << 5));
            uint4* dl = (uint4*)(sm + SM_WL + wr * SROW + (wq << 5));
#pragma unroll
            for (int i = 0; i < 2; i++) { dh[i] = sh[i]; dl[i] = sl[i]; }
        }
        __syncthreads();

#pragma unroll
        for (int k16 = 0; k16 < KC; k16 += 16) {
            unsigned ah[2][4], al[2][4], bh[4][2], bl[4][2];
            const int kb = (k16 + tig * 2) * 2;          // byte offset of k pair
#pragma unroll
            for (int mt = 0; mt < 2; mt++) {
                const int r0 = (wm * 32 + mt * 16 + gid) * SROW;
                ah[mt][0] = *(const unsigned*)(sm + SM_XH + r0 + kb);
                ah[mt][1] = *(const unsigned*)(sm + SM_XH + r0 + 8 * SROW + kb);
                ah[mt][2] = *(const unsigned*)(sm + SM_XH + r0 + kb + 16);
                ah[mt][3] = *(const unsigned*)(sm + SM_XH + r0 + 8 * SROW + kb + 16);
                al[mt][0] = *(const unsigned*)(sm + SM_XL + r0 + kb);
                al[mt][1] = *(const unsigned*)(sm + SM_XL + r0 + 8 * SROW + kb);
                al[mt][2] = *(const unsigned*)(sm + SM_XL + r0 + kb + 16);
                al[mt][3] = *(const unsigned*)(sm + SM_XL + r0 + 8 * SROW + kb + 16);
            }
#pragma unroll
            for (int nt = 0; nt < 4; nt++) {
                const int n0 = (wn * 32 + nt * 8 + gid) * SROW;
                bh[nt][0] = *(const unsigned*)(sm + SM_WH + n0 + kb);
                bh[nt][1] = *(const unsigned*)(sm + SM_WH + n0 + kb + 16);
                bl[nt][0] = *(const unsigned*)(sm + SM_WL + n0 + kb);
                bl[nt][1] = *(const unsigned*)(sm + SM_WL + n0 + kb + 16);
            }
#pragma unroll
            for (int mt = 0; mt < 2; mt++)
#pragma unroll
                for (int nt = 0; nt < 4; nt++) {
                    mma16816(acc[mt][nt], ah[mt], bh[nt]);
                    mma16816(acc[mt][nt], ah[mt], bl[nt]);
                    mma16816(acc[mt][nt], al[mt], bh[nt]);
                }
        }
    }

    __syncthreads();
    float* bias_s = (float*)sm;                  // reuse smem (compute done)
    if (tid < 64) bias_s[tid] = bih[bn + tid] + bhh[bn + tid];
    __syncthreads();

#pragma unroll
    for (int mt = 0; mt < 2; mt++) {
        const int r0 = bm + wm * 32 + mt * 16 + gid;
#pragma unroll
        for (int nt = 0; nt < 4; nt++) {
            const int col = wn * 32 + nt * 8 + tig * 2;
            const float b0 = bias_s[col], b1 = bias_s[col + 1];
            float2 o0 = make_float2(acc[mt][nt][0] + b0, acc[mt][nt][1] + b1);
            float2 o1 = make_float2(acc[mt][nt][2] + b0, acc[mt][nt][3] + b1);
            *(float2*)&g_xg[r0][bn + col]     = o0;
            *(float2*)&g_xg[r0 + 8][bn + col] = o1;
        }
    }
}

// ---- kernel 2: persistent LSTM recurrence + loss (R8 best, verbatim) ----
__global__ void __launch_bounds__(RTHREADS, 1) lstm_persist(const float* __restrict__ Whh) {
    const int b   = blockIdx.x;
    const int tid = threadIdx.x;

    if (b < NMV) {
        __shared__ float part[16][32];
        const int w = tid >> 5, l = tid & 31;
        // lane l -> gate (l>>3) in {i,f,g,o}, local row j = l&7; global j = 8b+(l&7)
        const int row = ((l >> 3) << 10) + (b << 3) + (l & 7);

        // This thread's 64 W_hh values in registers (cols 64w .. 64w+63).
        ulonglong2 Wr[16];
        {
            const ulonglong2* wp =
                (const ulonglong2*)(Whh + (size_t)row * HD + (w << 6));
#pragma unroll
            for (int q = 0; q < 16; q++) Wr[q] = wp[q];
        }
        float cstate = 0.f;              // warp0: replicated across 8-lane groups
        float xcur = 0.f;
        if (w == 0) xcur = g_xg[0][row];
        const int rep = b & 3;

        for (int t = 0; t < TT; t++) {
            if (t > 0) {
                if (tid == 0) wait_cnt(&g_cnt[t - 1][0]);
                __syncthreads();         // fan out: h_{t-1} visible
            }
            float psum = 0.f;
            if (t > 0) {
                const ulonglong2* hp =
                    (const ulonglong2*)(&g_hrep[rep][t - 1][w << 6]);
                unsigned long long a0 = 0ull, a1 = 0ull;
#pragma unroll
                for (int q = 0; q < 16; q++) {
                    ulonglong2 hh = hp[q];           // LDG.128, warp-uniform addr
                    a0 = ffma2(Wr[q].x, hh.x, a0);
                    a1 = ffma2(Wr[q].y, hh.y, a1);
                }
                float2 p0 = unpk(a0), p1 = unpk(a1);
                psum = (p0.x + p1.x) + (p0.y + p1.y);
            }
            part[w][l] = psum;
            __syncthreads();  // partials of step t visible to warp0

            if (w == 0) {
                float s0 = part[0][l]  + part[1][l];
                float s1 = part[2][l]  + part[3][l];
                float s2 = part[4][l]  + part[5][l];
                float s3 = part[6][l]  + part[7][l];
                float s4 = part[8][l]  + part[9][l];
                float s5 = part[10][l] + part[11][l];
                float s6 = part[12][l] + part[13][l];
                float s7 = part[14][l] + part[15][l];
                float u0 = (s0 + s1) + (s2 + s3);
                float u1 = (s4 + s5) + (s6 + s7);
                float gpre = xcur + (u0 + u1);

                // xcur consumed -> issue next step's DRAM prefetch NOW
                if (t + 1 < TT) xcur = g_xg[t + 1][row];

                // lane-parallel activations: gates i,f,o -> sigmoid; g -> tanh
                float act = ((l >> 3) == 2) ? tanha(gpre) : sigm(gpre);

                const int jj = l & 7;
                float ig = __shfl_sync(0xffffffffu, act, jj);
                float fg = __shfl_sync(0xffffffffu, act, jj + 8);
                float gg = __shfl_sync(0xffffffffu, act, jj + 16);
                float og = __shfl_sync(0xffffffffu, act, jj + 24);
                // every lane carries cstate/hv of row (l&7) -> identical per group
                cstate = fmaf(fg, cstate, ig * gg);
                float hv = og * tanha(cstate);
                g_hrep[l >> 3][t][(b << 3) + jj] = hv;   // ONE STG: 4 replicas
                __syncwarp();
                if (l == 0) red_rel(&g_cnt[t][0]);       // publish (release)
            }
        }
    } else {
        // ---- loss CTA (reads replica 0; off the critical path) ----
        __shared__ float sred[RTHREADS];
        const int lcta = b - NMV;
        for (int t = lcta; t < TT; t += NLOSS) {
            if (tid == 0) wait_cnt(&g_cnt[t][0]);
            __syncthreads();
            float v0 = g_hrep[0][t][2 * tid];
            float v1 = g_hrep[0][t][2 * tid + 1];
            sred[tid] = ex2f(v0 * L2E) + ex2f(v1 * L2E);
            __syncthreads();
            for (int s = RTHREADS / 2; s >= 32; s >>= 1) {
                if (tid < s) sred[tid] += sred[tid + s];
                __syncthreads();
            }
            if (tid < 32) {
                float v = sred[tid];
                v += __shfl_down_sync(0xffffffffu, v, 16);
                v += __shfl_down_sync(0xffffffffu, v, 8);
                v += __shfl_down_sync(0xffffffffu, v, 4);
                v += __shfl_down_sync(0xffffffffu, v, 2);
                v += __shfl_down_sync(0xffffffffu, v, 1);
                if (tid == 0) {
                    int y = g_ys[t];
                    g_loss[t] = __logf(v) - g_hrep[0][t][y];  // h in (-1,1)
                }
            }
            __syncthreads();
        }
    }
}

// ---- kernel 3: deterministic final sum ----
__global__ void __launch_bounds__(256) finalize_k(float* __restrict__ out) {
    __shared__ float sr[256];
    const int tid = threadIdx.x;
    float s = 0.f;
    for (int i = tid; i < TT; i += 256) s += g_loss[i];
    sr[tid] = s;
    __syncthreads();
    for (int st = 128; st >= 1; st >>= 1) {
        if (tid < st) sr[tid] += sr[tid + st];
        __syncthreads();
    }
    if (tid == 0) out[0] = sr[0];
}

// ---- entry point ----
extern "C" void kernel_launch(void* const* d_in, const int* in_sizes, int n_in,
                              void* d_out, int out_size) {
    const float* Xs  = (const float*)d_in[0];
    const float* Wih = (const float*)d_in[1];
    const float* Whh = (const float*)d_in[2];
    const float* bih = (const float*)d_in[3];
    const float* bhh = (const float*)d_in[4];
    const int*   ysr = (const int*)d_in[5];

    static int smset = 0;
    if (!smset) {
        cudaFuncSetAttribute(gemm_mma, cudaFuncAttributeMaxDynamicSharedMemorySize,
                             SM_GEMM);
        smset = 1;
    }

    reset_cnt<<<(TT * 32) / 256, 256>>>();
    reset_ys<<<TT / 256, 256>>>(ysr);
    prep_x<<<(TT * ED) / 256, 256>>>(Xs);
    prep_w<<<(G4 * ED) / 256, 256>>>(Wih);
    gemm_mma<<<dim3(G4 / 64, TT / 128), 256, SM_GEMM>>>(bih, bhh);
    lstm_persist<<<NMV + NLOSS, RTHREADS>>>(Whh);
    finalize_k<<<1, 256>>>((float*)d_out);
}

// round 16
// speedup vs baseline: 1.1095x; 1.0244x over previous
#include <cuda_runtime.h>
#include <cuda_bf16.h>
#include <cstdint>

#define TT   16384
#define ED   1024
#define HD   1024
#define G4   4096
#define NMV  128        // matvec CTAs (each owns 8 h-indices = 32 gate rows)
#define NLOSS 16        // dedicated loss CTAs
#define RTHREADS 512

// ---- scratch (static device memory; no allocations anywhere) ----
__device__ float         g_xg[TT][G4];       // 256 MB: input projections
__device__ float         g_hrep[4][TT][HD];  // 256 MB: h replicas (rep0 also feeds loss)
__device__ unsigned int  g_cnt[TT][32];      // 2 MB: per-step counter, ONE per 128B line
__device__ float         g_loss[TT];         // per-step losses
__device__ int           g_ys[TT];           // normalized labels (int32)
__device__ __nv_bfloat16 g_Xhi[TT * ED];     // bf16 splits of Xs
__device__ __nv_bfloat16 g_Xlo[TT * ED];
__device__ __nv_bfloat16 g_Whi[G4 * ED];     // bf16 splits of W_ih
__device__ __nv_bfloat16 g_Wlo[G4 * ED];

// ---- helpers ----
__device__ __forceinline__ unsigned long long ffma2(unsigned long long a,
                                                    unsigned long long b,
                                                    unsigned long long c) {
    unsigned long long d;
    asm("fma.rn.f32x2 %0, %1, %2, %3;" : "=l"(d) : "l"(a), "l"(b), "l"(c));
    return d;
}
__device__ __forceinline__ float2 unpk(unsigned long long v) {
    float2 r;
    asm("mov.b64 {%0, %1}, %2;" : "=f"(r.x), "=f"(r.y) : "l"(v));
    return r;
}
__device__ __forceinline__ unsigned int ld_acq(const unsigned int* p) {
    unsigned int v;
    asm volatile("ld.acquire.gpu.global.u32 %0, [%1];" : "=r"(v) : "l"(p) : "memory");
    return v;
}
__device__ __forceinline__ void red_rel(unsigned int* p) {
    asm volatile("red.release.gpu.global.add.u32 [%0], 1;" :: "l"(p) : "memory");
}
// tid0-only wait: acquire-poll. The round that OBSERVES cnt==NMV is itself the
// ordering point (reads the final value of the RMW release sequence) -> no
// separate confirm round-trip on the critical path.
__device__ __forceinline__ void wait_cnt(const unsigned int* p) {
    while (ld_acq(p) < NMV) { }
}
__device__ __forceinline__ float ex2f(float x) {
    float y; asm("ex2.approx.f32 %0, %1;" : "=f"(y) : "f"(x)); return y;
}
__device__ __forceinline__ float rcpf(float x) {
    float y; asm("rcp.approx.f32 %0, %1;" : "=f"(y) : "f"(x)); return y;
}
#define L2E 1.4426950408889634f
__device__ __forceinline__ float sigm(float x) {           // 1/(1+e^-x)
    return rcpf(1.f + ex2f(-x * L2E));
}
__device__ __forceinline__ float tanha(float x) {          // 1 - 2/(e^{2x}+1)
    return fmaf(-2.f, rcpf(1.f + ex2f(x * (2.f * L2E))), 1.f);
}
// m16n8k16 row.col bf16 MMA, fp32 accumulate (PTX-standard since sm_80)
__device__ __forceinline__ void mma16816(float* d, const unsigned* a, const unsigned* b) {
    asm volatile("mma.sync.aligned.m16n8k16.row.col.f32.bf16.bf16.f32 "
                 "{%0,%1,%2,%3}, {%4,%5,%6,%7}, {%8,%9}, {%0,%1,%2,%3};"
                 : "+f"(d[0]), "+f"(d[1]), "+f"(d[2]), "+f"(d[3])
                 : "r"(a[0]), "r"(a[1]), "r"(a[2]), "r"(a[3]),
                   "r"(b[0]), "r"(b[1]));
}

// ---- kernel 0: reset padded counters ----
__global__ void __launch_bounds__(256) reset_cnt() {
    (&g_cnt[0][0])[blockIdx.x * 256 + threadIdx.x] = 0u;   // TT*32 words
}
// ---- kernel 0b: normalize ys dtype (int64 vs int32 autodetect) ----
__global__ void __launch_bounds__(256) reset_ys(const int* __restrict__ ysr) {
    int i = blockIdx.x * 256 + threadIdx.x;
    bool is64 = true;
#pragma unroll
    for (int q = 1; q < 16; q += 2) is64 = is64 && (ysr[q] == 0);
    if (i < TT) g_ys[i] = is64 ? ysr[2 * i] : ysr[i];
}
// ---- kernel 0c: fp32 -> (bf16 hi, bf16 lo) splits, X and W in one launch ----
__global__ void __launch_bounds__(256) prep_split(const float* __restrict__ X,
                                                  const float* __restrict__ W) {
    int i = blockIdx.x * 256 + threadIdx.x;
    if (i < TT * ED) {
        float x = X[i];
        __nv_bfloat16 hi = __float2bfloat16_rn(x);
        g_Xhi[i] = hi;
        g_Xlo[i] = __float2bfloat16_rn(x - __bfloat162float(hi));
    } else {
        int j = i - TT * ED;
        float x = W[j];
        __nv_bfloat16 hi = __float2bfloat16_rn(x);
        g_Whi[j] = hi;
        g_Wlo[j] = __float2bfloat16_rn(x - __bfloat162float(hi));
    }
}

// ---- kernel 1: xg = Xs @ W_ih^T + b via bf16-split HMMA (mma.sync) ----
// CTA tile 128(M) x 128(N), 8 warps (4x2), warp tile 32x64 = 2(m16) x 8(n8).
// K chunk 64; D = Ahi*Bhi + Ahi*Blo + Alo*Bhi, fp32 accumulators.
// SMEM rows padded to 72 bf16 (144B): bank = 4*gid + tig -> conflict-free.
#define KC    64
#define SROW  144                         // smem row stride in bytes (72 bf16)
#define SM_XH 0
#define SM_XL (128 * SROW)                // 18432
#define SM_WH (2 * 128 * SROW)            // 36864
#define SM_WL (3 * 128 * SROW)            // 55296
#define SM_GEMM (4 * 128 * SROW)          // 73728 bytes dynamic smem

__global__ void __launch_bounds__(256) gemm_mma(const float* __restrict__ bih,
                                                const float* __restrict__ bhh) {
    extern __shared__ char sm[];
    const int tid  = threadIdx.x;
    const int bn   = blockIdx.x * 128;    // gate rows (N)
    const int bm   = blockIdx.y * 128;    // T rows (M)
    const int lane = tid & 31;
    const int ww   = tid >> 5;
    const int gid  = lane >> 2, tig = lane & 3;
    const int wm   = ww & 3,  wn  = ww >> 2;

    float acc[2][8][4];
#pragma unroll
    for (int mt = 0; mt < 2; mt++)
#pragma unroll
        for (int nt = 0; nt < 8; nt++)
#pragma unroll
            for (int r = 0; r < 4; r++) acc[mt][nt][r] = 0.f;

    const int xr = tid >> 1, xh = tid & 1;     // copies: row, 32-col half

    for (int kc = 0; kc < ED; kc += KC) {
        __syncthreads();                       // previous compute done with smem
        {   // X slabs: 128 rows x 64 cols bf16 (hi & lo)
            size_t gs = ((size_t)(bm + xr) << 10) + kc + (xh << 5);
            const uint4* shp = (const uint4*)&g_Xhi[gs];
            const uint4* slp = (const uint4*)&g_Xlo[gs];
            uint4* dh = (uint4*)(sm + SM_XH + xr * SROW + (xh << 6));
            uint4* dl = (uint4*)(sm + SM_XL + xr * SROW + (xh << 6));
#pragma unroll
            for (int i = 0; i < 4; i++) { dh[i] = shp[i]; dl[i] = slp[i]; }
        }
        {   // W slabs: 128 rows x 64 cols bf16 (hi & lo)
            size_t gs = ((size_t)(bn + xr) << 10) + kc + (xh << 5);
            const uint4* shp = (const uint4*)&g_Whi[gs];
            const uint4* slp = (const uint4*)&g_Wlo[gs];
            uint4* dh = (uint4*)(sm + SM_WH + xr * SROW + (xh << 6));
            uint4* dl = (uint4*)(sm + SM_WL + xr * SROW + (xh << 6));
#pragma unroll
            for (int i = 0; i < 4; i++) { dh[i] = shp[i]; dl[i] = slp[i]; }
        }
        __syncthreads();

#pragma unroll
        for (int k16 = 0; k16 < KC; k16 += 16) {
            unsigned ah[2][4], al[2][4], bh[8][2], bl[8][2];
            const int kb = (k16 + tig * 2) * 2;          // byte offset of k pair
#pragma unroll
            for (int mt = 0; mt < 2; mt++) {
                const int r0 = (wm * 32 + mt * 16 + gid) * SROW;
                ah[mt][0] = *(const unsigned*)(sm + SM_XH + r0 + kb);
                ah[mt][1] = *(const unsigned*)(sm + SM_XH + r0 + 8 * SROW + kb);
                ah[mt][2] = *(const unsigned*)(sm + SM_XH + r0 + kb + 16);
                ah[mt][3] = *(const unsigned*)(sm + SM_XH + r0 + 8 * SROW + kb + 16);
                al[mt][0] = *(const unsigned*)(sm + SM_XL + r0 + kb);
                al[mt][1] = *(const unsigned*)(sm + SM_XL + r0 + 8 * SROW + kb);
                al[mt][2] = *(const unsigned*)(sm + SM_XL + r0 + kb + 16);
                al[mt][3] = *(const unsigned*)(sm + SM_XL + r0 + 8 * SROW + kb + 16);
            }
#pragma unroll
            for (int nt = 0; nt < 8; nt++) {
                const int n0 = (wn * 64 + nt * 8 + gid) * SROW;
                bh[nt][0] = *(const unsigned*)(sm + SM_WH + n0 + kb);
                bh[nt][1] = *(const unsigned*)(sm + SM_WH + n0 + kb + 16);
                bl[nt][0] = *(const unsigned*)(sm + SM_WL + n0 + kb);
                bl[nt][1] = *(const unsigned*)(sm + SM_WL + n0 + kb + 16);
            }
#pragma unroll
            for (int mt = 0; mt < 2; mt++)
#pragma unroll
                for (int nt = 0; nt < 8; nt++) {
                    mma16816(acc[mt][nt], ah[mt], bh[nt]);
                    mma16816(acc[mt][nt], ah[mt], bl[nt]);
                    mma16816(acc[mt][nt], al[mt], bh[nt]);
                }
        }
    }

    __syncthreads();
    float* bias_s = (float*)sm;                  // reuse smem (compute done)
    if (tid < 128) bias_s[tid] = bih[bn + tid] + bhh[bn + tid];
    __syncthreads();

#pragma unroll
    for (int mt = 0; mt < 2; mt++) {
        const int r0 = bm + wm * 32 + mt * 16 + gid;
#pragma unroll
        for (int nt = 0; nt < 8; nt++) {
            const int col = wn * 64 + nt * 8 + tig * 2;
            const float b0 = bias_s[col], b1 = bias_s[col + 1];
            float2 o0 = make_float2(acc[mt][nt][0] + b0, acc[mt][nt][1] + b1);
            float2 o1 = make_float2(acc[mt][nt][2] + b0, acc[mt][nt][3] + b1);
            *(float2*)&g_xg[r0][bn + col]     = o0;
            *(float2*)&g_xg[r0 + 8][bn + col] = o1;
        }
    }
}

// ---- kernel 2: persistent LSTM recurrence + loss (R8 skeleton) ----
__global__ void __launch_bounds__(RTHREADS, 1) lstm_persist(const float* __restrict__ Whh) {
    const int b   = blockIdx.x;
    const int tid = threadIdx.x;

    if (b < NMV) {
        __shared__ float part[16][32];
        const int w = tid >> 5, l = tid & 31;
        // lane l -> gate (l>>3) in {i,f,g,o}, local row j = l&7; global j = 8b+(l&7)
        const int row = ((l >> 3) << 10) + (b << 3) + (l & 7);

        // This thread's 64 W_hh values in registers (cols 64w .. 64w+63).
        ulonglong2 Wr[16];
        {
            const ulonglong2* wp =
                (const ulonglong2*)(Whh + (size_t)row * HD + (w << 6));
#pragma unroll
            for (int q = 0; q < 16; q++) Wr[q] = wp[q];
        }
        float cstate = 0.f;              // warp0: replicated across 8-lane groups
        float xcur = 0.f;
        if (w == 0) xcur = g_xg[0][row];
        const int rep = b & 3;

        for (int t = 0; t < TT; t++) {
            if (t > 0) {
                if (tid == 0) wait_cnt(&g_cnt[t - 1][0]);
                __syncthreads();         // fan out: h_{t-1} visible
            }
            float psum = 0.f;
            if (t > 0) {
                const ulonglong2* hp =
                    (const ulonglong2*)(&g_hrep[rep][t - 1][w << 6]);
                unsigned long long a0 = 0ull, a1 = 0ull;
#pragma unroll
                for (int q = 0; q < 16; q++) {
                    ulonglong2 hh = hp[q];           // LDG.128, warp-uniform addr
                    a0 = ffma2(Wr[q].x, hh.x, a0);
                    a1 = ffma2(Wr[q].y, hh.y, a1);
                }
                float2 p0 = unpk(a0), p1 = unpk(a1);
                psum = (p0.x + p1.x) + (p0.y + p1.y);
            }
            part[w][l] = psum;
            __syncthreads();  // partials of step t visible to warp0

            if (w == 0) {
                float s0 = part[0][l]  + part[1][l];
                float s1 = part[2][l]  + part[3][l];
                float s2 = part[4][l]  + part[5][l];
                float s3 = part[6][l]  + part[7][l];
                float s4 = part[8][l]  + part[9][l];
                float s5 = part[10][l] + part[11][l];
                float s6 = part[12][l] + part[13][l];
                float s7 = part[14][l] + part[15][l];
                float u0 = (s0 + s1) + (s2 + s3);
                float u1 = (s4 + s5) + (s6 + s7);
                float gpre = xcur + (u0 + u1);

                // xcur consumed -> issue next step's DRAM prefetch NOW
                if (t + 1 < TT) xcur = g_xg[t + 1][row];

                // lane-parallel activations: gates i,f,o -> sigmoid; g -> tanh
                float act = ((l >> 3) == 2) ? tanha(gpre) : sigm(gpre);

                const int jj = l & 7;
                float ig = __shfl_sync(0xffffffffu, act, jj);
                float fg = __shfl_sync(0xffffffffu, act, jj + 8);
                float gg = __shfl_sync(0xffffffffu, act, jj + 16);
                float og = __shfl_sync(0xffffffffu, act, jj + 24);
                // every lane carries cstate/hv of row (l&7) -> identical per group
                cstate = fmaf(fg, cstate, ig * gg);
                float hv = og * tanha(cstate);
                g_hrep[l >> 3][t][(b << 3) + jj] = hv;   // ONE STG: 4 replicas
                __syncwarp();
                if (l == 0) red_rel(&g_cnt[t][0]);       // publish (release)
            }
        }
    } else {
        // ---- loss CTA (reads replica 0; off the critical path) ----
        __shared__ float sred[RTHREADS];
        const int lcta = b - NMV;
        for (int t = lcta; t < TT; t += NLOSS) {
            if (tid == 0) wait_cnt(&g_cnt[t][0]);
            __syncthreads();
            float v0 = g_hrep[0][t][2 * tid];
            float v1 = g_hrep[0][t][2 * tid + 1];
            sred[tid] = ex2f(v0 * L2E) + ex2f(v1 * L2E);
            __syncthreads();
            for (int s = RTHREADS / 2; s >= 32; s >>= 1) {
                if (tid < s) sred[tid] += sred[tid + s];
                __syncthreads();
            }
            if (tid < 32) {
                float v = sred[tid];
                v += __shfl_down_sync(0xffffffffu, v, 16);
                v += __shfl_down_sync(0xffffffffu, v, 8);
                v += __shfl_down_sync(0xffffffffu, v, 4);
                v += __shfl_down_sync(0xffffffffu, v, 2);
                v += __shfl_down_sync(0xffffffffu, v, 1);
                if (tid == 0) {
                    int y = g_ys[t];
                    g_loss[t] = __logf(v) - g_hrep[0][t][y];  // h in (-1,1)
                }
            }
            __syncthreads();
        }
    }
}

// ---- kernel 3: deterministic final sum ----
__global__ void __launch_bounds__(256) finalize_k(float* __restrict__ out) {
    __shared__ float sr[256];
    const int tid = threadIdx.x;
    float s = 0.f;
    for (int i = tid; i < TT; i += 256) s += g_loss[i];
    sr[tid] = s;
    __syncthreads();
    for (int st = 128; st >= 1; st >>= 1) {
        if (tid < st) sr[tid] += sr[tid + st];
        __syncthreads();
    }
    if (tid == 0) out[0] = sr[0];
}

// ---- entry point ----
extern "C" void kernel_launch(void* const* d_in, const int* in_sizes, int n_in,
                              void* d_out, int out_size) {
    const float* Xs  = (const float*)d_in[0];
    const float* Wih = (const float*)d_in[1];
    const float* Whh = (const float*)d_in[2];
    const float* bih = (const float*)d_in[3];
    const float* bhh = (const float*)d_in[4];
    const int*   ysr = (const int*)d_in[5];

    static int smset = 0;
    if (!smset) {
        cudaFuncSetAttribute(gemm_mma, cudaFuncAttributeMaxDynamicSharedMemorySize,
                             SM_GEMM);
        smset = 1;
    }

    reset_cnt<<<(TT * 32) / 256, 256>>>();
    reset_ys<<<TT / 256, 256>>>(ysr);
    prep_split<<<((TT + G4) * ED) / 256, 256>>>(Xs, Wih);
    gemm_mma<<<dim3(G4 / 128, TT / 128), 256, SM_GEMM>>>(bih, bhh);
    lstm_persist<<<NMV + NLOSS, RTHREADS>>>(Whh);
    finalize_k<<<1, 256>>>((float*)d_out);
}